// round 16
// baseline (speedup 1.0000x reference)
#include <cuda_runtime.h>
#include <cuda_fp16.h>
#include <cstdint>

// LinearMPC: u' = clip(G u + c), G = I - 0.01 H (512x512), batch 2048, 100 iters.
// mma.sync m16n8k16 fp16 hi/lo split (3 terms), fp32 accumulate.
// R15: c held in registers (no cs smem / LDS); u exchange via cp.async.cg from
// a scratch mirrored in smem layout; own-slice MMA s-steps run while peer
// slices stream in asynchronously. 64 tiles x cluster 4 = 256 CTAs, 2/SM.

#define MDIM 512
#define BATCH 2048
#define TILE_B 32
#define CLUSTER 4
#define NCTAS 256
#define NTHREADS 256               // 8 warps, warp w owns m-tile w (16 rows)
#define XREF_STRIDE 520

#define U_PITCH 520                // halves per u row (512 + 8 pad), 1040B = 65*16
// SMEM layout (bytes)
#define SM_UHI 0
#define SM_ULO (TILE_B * U_PITCH * 2)          // 33280
#define SM_TOTAL (2 * TILE_B * U_PITCH * 2)    // 66560

// Fragment-packed G: frag uint4 idx = (((slice*8+mtile)*2 + p)*32 + s)*32 + lane
__device__ __half g_Afrag[512 * 512 * 2];      // 1 MB
// u scratch, hi/lo separated, [buf][row][k] tight pitch 512 halves
__device__ __half g_uh[2][BATCH * MDIM];
__device__ __half g_ul[2][BATCH * MDIM];

__global__ void init_G_kernel(const float* __restrict__ H) {
    int m = blockIdx.x;            // output row
    int k = threadIdx.x;           // K index
    float g = -0.01f * H[m * MDIM + k];
    if (m == k) g += 1.0f;
    __half hi = __float2half(g);
    __half lo = __float2half(g - __half2float(hi));
    int slice = m >> 7, mloc = m & 127, mtile = mloc >> 4, r = mloc & 15;
    int s = k >> 4, kin = k & 15;
    int L = (r & 7) * 4 + ((kin & 7) >> 1);
    int reg = (r >> 3) + 2 * (kin >> 3);
    int hf = kin & 1;
#pragma unroll
    for (int p = 0; p < 2; ++p) {
        long idx = ((((long)((slice * 8 + mtile) * 2 + p)) * 32 + s) * 32 + L) * 8
                   + reg * 2 + hf;
        g_Afrag[idx] = p ? lo : hi;
    }
}

// ---------------- helpers ----------------
__device__ __forceinline__ uint32_t smem_u32(const void* p) {
    uint32_t a;
    asm("{ .reg .u64 t; cvta.to.shared.u64 t, %1; cvt.u32.u64 %0, t; }"
        : "=r"(a) : "l"(p));
    return a;
}
__device__ __forceinline__ uint32_t cluster_rank() {
    uint32_t r; asm("mov.u32 %0, %%cluster_ctarank;" : "=r"(r)); return r;
}
#define CLUSTER_SYNC() do {                                           \
    asm volatile("barrier.cluster.arrive.aligned;" ::: "memory");     \
    asm volatile("barrier.cluster.wait.aligned;" ::: "memory"); } while (0)

#define LDM_X4(r0, r1, r2, r3, addr) \
    asm volatile("ldmatrix.sync.aligned.m8n8.x4.shared.b16 {%0,%1,%2,%3}, [%4];" \
        : "=r"(r0), "=r"(r1), "=r"(r2), "=r"(r3) : "r"(addr))

#define MMA16816(d, a, b0, b1) \
    asm volatile("mma.sync.aligned.m16n8k16.row.col.f32.f16.f16.f32 " \
        "{%0,%1,%2,%3}, {%4,%5,%6,%7}, {%8,%9}, {%0,%1,%2,%3};" \
        : "+f"((d)[0]), "+f"((d)[1]), "+f"((d)[2]), "+f"((d)[3]) \
        : "r"((a).x), "r"((a).y), "r"((a).z), "r"((a).w), "r"(b0), "r"(b1))

__device__ __forceinline__ float clip1(float x) {
    return fminf(fmaxf(x, -1.0f), 1.0f);
}
__device__ __forceinline__ void stg16(__half* p, __half v) {
    asm volatile("st.global.cg.b16 [%0], %1;"
                 :: "l"(p), "h"(__half_as_ushort(v)) : "memory");
}

// one K=16 step: 2 A LDG.128 + 4 LDSM.x4 + 12 HMMA
__device__ __forceinline__ void mma_step(float (&D)[4][4], int s,
                                         const uint4* __restrict__ gA, int baseA,
                                         uint32_t bH0, uint32_t bH1,
                                         uint32_t bL0, uint32_t bL1) {
    uint4 Ah = __ldg(gA + baseA + s * 32);
    uint4 Al = __ldg(gA + baseA + 1024 + s * 32);
    uint32_t Bh[8], Bl[8];
    uint32_t o = (uint32_t)s * 32;
    LDM_X4(Bh[0], Bh[1], Bh[2], Bh[3], bH0 + o);
    LDM_X4(Bh[4], Bh[5], Bh[6], Bh[7], bH1 + o);
    LDM_X4(Bl[0], Bl[1], Bl[2], Bl[3], bL0 + o);
    LDM_X4(Bl[4], Bl[5], Bl[6], Bl[7], bL1 + o);
#pragma unroll
    for (int nt = 0; nt < 4; ++nt)
        MMA16816(D[nt], Ah, Bh[nt * 2], Bh[nt * 2 + 1]);   // Ghi*uhi
#pragma unroll
    for (int nt = 0; nt < 4; ++nt)
        MMA16816(D[nt], Ah, Bl[nt * 2], Bl[nt * 2 + 1]);   // Ghi*ulo
#pragma unroll
    for (int nt = 0; nt < 4; ++nt)
        MMA16816(D[nt], Al, Bh[nt * 2], Bh[nt * 2 + 1]);   // Glo*uhi
}

extern "C" __global__ void __launch_bounds__(NTHREADS, 2) __cluster_dims__(CLUSTER, 1, 1)
mpc_mma_kernel(const float* __restrict__ xref,
               const float* __restrict__ Phi,
               const float* __restrict__ Q,
               float* __restrict__ out) {
    extern __shared__ char smem[];
    const uint32_t sb = smem_u32(smem);
    __half* smemH = (__half*)(smem + SM_UHI);
    __half* smemL = (__half*)(smem + SM_ULO);

    const int tid = threadIdx.x;
    const int wid = tid >> 5;                // m-tile 0..7
    const int lane = tid & 31;
    const int slice = (int)cluster_rank();   // output column slice 0..3
    const int tile = blockIdx.x >> 2;        // batch tile 0..63

    const int g = lane >> 2, cq = lane & 3;  // D frag coords

    // ---- phase 1: per-thread c values (16), registers only ----
    // C[nt][e]: e>>1 selects m (+8), e&1 selects n (+1)
    float C[4][4];
    {
        const int m0g = slice * 128 + wid * 16 + g;      // global col, +8 for mi=1
#pragma unroll
        for (int nt = 0; nt < 4; ++nt) {
#pragma unroll
            for (int npar = 0; npar < 2; ++npar) {
                int n = nt * 8 + 2 * cq + npar;
                const float* xr = xref + (long)(tile * TILE_B + n) * XREF_STRIDE;
                float x0[8];
#pragma unroll
                for (int l = 0; l < 8; ++l) x0[l] = xr[l];
#pragma unroll
                for (int mi = 0; mi < 2; ++mi) {
                    int M = m0g + mi * 8;
                    int kblk = M >> 3, i = M & 7;
                    float dx[8];
#pragma unroll
                    for (int l = 0; l < 8; ++l)
                        dx[l] = xr[kblk * 8 + l] - x0[l];
                    float qdx[8];
#pragma unroll
                    for (int j = 0; j < 8; ++j) {
                        float s = 0.0f;
#pragma unroll
                        for (int l = 0; l < 8; ++l) s += Q[j * 8 + l] * dx[l];
                        qdx[j] = s;
                    }
                    float s = 0.0f;
#pragma unroll
                    for (int j = 0; j < 8; ++j)
                        s += Phi[kblk * 64 + i * 8 + j] * qdx[j];
                    C[nt][mi * 2 + npar] = 0.02f * s;
                }
            }
        }
    }

    // ---- B ldmatrix base addresses ----
    const int q = lane >> 3, rr = lane & 7;
    const int brow = (q >> 1) * 8 + rr;
    const int bkoff = (q & 1) * 8;
    const uint32_t bH0 = sb + SM_UHI + (uint32_t)(brow * (U_PITCH * 2) + bkoff * 2);
    const uint32_t bH1 = bH0 + 16 * (U_PITCH * 2);
    const uint32_t bL0 = bH0 + (SM_ULO - SM_UHI);
    const uint32_t bL1 = bH1 + (SM_ULO - SM_UHI);

    const uint4* gA = (const uint4*)g_Afrag;
    const int baseA = ((slice * 8 + wid) * 2) * 1024 + lane;
    const int own0 = slice * 8;              // own k-range s-steps [own0, own0+8)

    float D[4][4];
#pragma unroll
    for (int nt = 0; nt < 4; ++nt)
#pragma unroll
        for (int e = 0; e < 4; ++e) D[nt][e] = 0.0f;

    for (int it = 0; it < 100; ++it) {
        __syncthreads();                     // prior MMA smem reads complete
        const bool last = (it == 99);
        const int nb = it & 1;

        // ---- emit V = clip(D + C) ----
#pragma unroll
        for (int nt = 0; nt < 4; ++nt) {
#pragma unroll
            for (int e = 0; e < 4; ++e) {
                int m = wid * 16 + g + (e >> 1) * 8;     // local m 0..127
                int n = nt * 8 + 2 * cq + (e & 1);       // local n 0..31
                int M = slice * 128 + m;                 // global col
                float v = clip1(D[nt][e] + C[nt][e]);
                if (last) {
                    out[(long)(tile * TILE_B + n) * MDIM + M] = v;
                } else {
                    __half hi = __float2half(v);
                    __half lo = __float2half(v - __half2float(hi));
                    smemH[n * U_PITCH + M] = hi;         // own slice direct
                    smemL[n * U_PITCH + M] = lo;
                    long gi = (long)(tile * TILE_B + n) * MDIM + M;
                    stg16(&g_uh[nb][gi], hi);            // peers read via cp.async
                    stg16(&g_ul[nb][gi], lo);
                }
            }
        }
        if (last) break;

        __threadfence();
        CLUSTER_SYNC();

        // ---- async fetch of the 3 peer slices into smem ----
        // 3072 x 16B chunks: a(2 arrays) x n(32) x 48 chunks (3 peers x 16)
#pragma unroll
        for (int o = 0; o < 12; ++o) {
            int id = o * 256 + tid;
            int a = (id >= 1536) ? 1 : 0;
            int rem = id - a * 1536;
            int n2 = rem / 48;
            int ch = rem - n2 * 48;
            int pb = ch >> 4, ci = ch & 15;
            int ps = pb + (pb >= slice ? 1 : 0);
            int k0 = ps * 128 + ci * 8;
            const __half* src = (a ? g_ul[nb] : g_uh[nb])
                                + (long)(tile * TILE_B + n2) * MDIM + k0;
            uint32_t dst = sb + (a ? SM_ULO : SM_UHI)
                           + (uint32_t)(n2 * U_PITCH + k0) * 2;
            asm volatile("cp.async.cg.shared.global [%0], [%1], 16;"
                         :: "r"(dst), "l"(src) : "memory");
        }
        asm volatile("cp.async.commit_group;" ::: "memory");
        __syncthreads();                     // own-slice STS visible to all warps

#pragma unroll
        for (int nt = 0; nt < 4; ++nt)
#pragma unroll
            for (int e = 0; e < 4; ++e) D[nt][e] = 0.0f;

        // ---- MMA own k-range while peer slices land ----
#pragma unroll
        for (int so = 0; so < 8; ++so)
            mma_step(D, own0 + so, gA, baseA, bH0, bH1, bL0, bL1);

        asm volatile("cp.async.wait_group 0;" ::: "memory");
        __syncthreads();                     // peer data visible everywhere

        // ---- MMA remaining 24 s-steps ----
#pragma unroll 4
        for (int sx = 0; sx < 24; ++sx) {
            int s = sx + (sx >= own0 ? 8 : 0);
            mma_step(D, s, gA, baseA, bH0, bH1, bL0, bL1);
        }
    }
}

extern "C" void kernel_launch(void* const* d_in, const int* in_sizes, int n_in,
                              void* d_out, int out_size) {
    // inputs: x0 (unused), xref, H, Phi, Q
    const float* xref = (const float*)d_in[1];
    const float* H    = (const float*)d_in[2];
    const float* Phi  = (const float*)d_in[3];
    const float* Q    = (const float*)d_in[4];
    float* out = (float*)d_out;

    cudaFuncSetAttribute(mpc_mma_kernel,
                         cudaFuncAttributeMaxDynamicSharedMemorySize, SM_TOTAL);

    init_G_kernel<<<MDIM, MDIM>>>(H);
    mpc_mma_kernel<<<NCTAS, NTHREADS, SM_TOTAL>>>(xref, Phi, Q, out);
}